// round 12
// baseline (speedup 1.0000x reference)
#include <cuda_runtime.h>
#include <cuda_fp16.h>
#include <cstdint>

#define NMAX 100000
#define EMAX 1600000
#define IND 128
#define HID 128
#define OUTD 64
#define SCAN_B 1024
#define MAXBLK 128

// ---------------- scratch (static __device__, allocation-free) ----------------
__device__ int   g_degc[NMAX];
__device__ float g_dinv[NMAX];
__device__ int   g_rowptr[NMAX + 1];
__device__ int   g_pos[NMAX];
__device__ int   g_csr_src[EMAX];
__device__ unsigned long long g_scan_state[MAXBLK];  // (flag<<32)|value; 0=invalid,1=agg,2=prefix
__device__ __half g_x16[(size_t)NMAX * IND];    // x * dinv, f16 (gather table L1)
__device__ __half g_agg16[(size_t)NMAX * IND];  // layer-1 aggregate, f16 (GEMM A)
__device__ __half g_h216[(size_t)NMAX * OUTD];  // h2 * dinv, f16 (gather table L2)
// W pre-transposed to [n][k] f16 hi/lo (hi + lo == fp32 weight to ~2^-22)
__device__ __half g_w1hi[HID * IND];
__device__ __half g_w1lo[HID * IND];
__device__ __half g_w2hi[OUTD * IND];
__device__ __half g_w2lo[OUTD * IND];

__device__ __forceinline__ uint32_t smem_u32(const void* p) {
    uint32_t a;
    asm("{ .reg .u64 t; cvta.to.shared.u64 t, %1; cvt.u32.u64 %0, t; }" : "=r"(a) : "l"(p));
    return a;
}
__device__ __forceinline__ void ldm_x4(uint32_t* r, uint32_t addr) {
    asm volatile("ldmatrix.sync.aligned.m8n8.x4.shared.b16 {%0,%1,%2,%3}, [%4];"
                 : "=r"(r[0]), "=r"(r[1]), "=r"(r[2]), "=r"(r[3]) : "r"(addr));
}
__device__ __forceinline__ void mma16816(float* d, const uint32_t* a, const uint32_t* b) {
    asm volatile(
        "mma.sync.aligned.m16n8k16.row.col.f32.f16.f16.f32 "
        "{%0,%1,%2,%3}, {%4,%5,%6,%7}, {%8,%9}, {%0,%1,%2,%3};"
        : "+f"(d[0]), "+f"(d[1]), "+f"(d[2]), "+f"(d[3])
        : "r"(a[0]), "r"(a[1]), "r"(a[2]), "r"(a[3]), "r"(b[0]), "r"(b[1]));
}
__device__ __forceinline__ void split_h(float v, __half& hi, __half& lo) {
    hi = __float2half_rn(v);
    lo = __float2half_rn(v - __half2float(hi));
}
__device__ __forceinline__ unsigned long long ldvol64(const unsigned long long* p) {
    unsigned long long v;
    asm volatile("ld.volatile.global.u64 %0, [%1];" : "=l"(v) : "l"(p));
    return v;
}
__device__ __forceinline__ void stvol64(unsigned long long* p, unsigned long long v) {
    asm volatile("st.volatile.global.u64 [%0], %1;" :: "l"(p), "l"(v));
}
__device__ __forceinline__ __half2 u2h(uint32_t u) { return *(__half2*)&u; }

// ---------------- CSR build ----------------
// NOTE: g_degc is zeroed by agg2_k at the end of each replay (and statically for call 1).
__global__ void deg4_k(const int* __restrict__ dst, int E4, int E) {
    int i = blockIdx.x * blockDim.x + threadIdx.x;
    if (i < MAXBLK) g_scan_state[i] = 0ULL;   // reset lookback state for this replay
    if (i < E4) {
        int4 d = ((const int4*)dst)[i];
        atomicAdd(&g_degc[d.x], 1);
        atomicAdd(&g_degc[d.y], 1);
        atomicAdd(&g_degc[d.z], 1);
        atomicAdd(&g_degc[d.w], 1);
    }
    if (i == 0)
        for (int k = E4 * 4; k < E; k++) atomicAdd(&g_degc[dst[k]], 1);
}
__global__ void deg_k(const int* __restrict__ dst, int E) {
    int i = blockIdx.x * blockDim.x + threadIdx.x;
    if (i < MAXBLK) g_scan_state[i] = 0ULL;
    if (i < E) atomicAdd(&g_degc[dst[i]], 1);
}

// Single-kernel exclusive scan (decoupled lookback) + dinv + x16 conversion.
// Grid must be <= 148 blocks (co-residency). Block b owns rows [b*1024, b*1024+1024).
__global__ __launch_bounds__(SCAN_B) void scanx_k(const float* __restrict__ x, int n) {
    __shared__ int wsum[32];
    __shared__ int sprefix;
    int b = blockIdx.x, t = threadIdx.x;
    int i = b * SCAN_B + t;
    int v = (i < n) ? g_degc[i] : 0;
    if (i < n) g_dinv[i] = rsqrtf((float)v + 1.0f);
    int lane = t & 31, w = t >> 5;
    int x_ = v;
#pragma unroll
    for (int o = 1; o < 32; o <<= 1) {
        int y = __shfl_up_sync(0xffffffffu, x_, o);
        if (lane >= o) x_ += y;
    }
    if (lane == 31) wsum[w] = x_;
    __syncthreads();
    if (w == 0) {
        int s = wsum[lane];
#pragma unroll
        for (int o = 1; o < 32; o <<= 1) {
            int y = __shfl_up_sync(0xffffffffu, s, o);
            if (lane >= o) s += y;
        }
        wsum[lane] = s;
    }
    __syncthreads();
    int incl = x_ + (w > 0 ? wsum[w - 1] : 0);
    int total = wsum[31];

    if (w == 0) {
        if (lane == 0)
            stvol64(&g_scan_state[b],
                    ((unsigned long long)((b == 0) ? 2u : 1u) << 32) | (unsigned)total);
        __syncwarp();
        if (b > 0) {
            int P = 0;
            int i0 = b - 1;
            while (true) {
                int ii = i0 - lane;
                unsigned long long s = (ii >= 0) ? ldvol64(&g_scan_state[ii])
                                                 : (2ULL << 32);
                while (__any_sync(0xffffffffu, (s >> 32) == 0))
                    if ((s >> 32) == 0) s = ldvol64(&g_scan_state[ii]);
                int f = (int)(s >> 32);
                int val = (int)(unsigned)s;
                unsigned m = __ballot_sync(0xffffffffu, f == 2);
                int c;
                if (m) {
                    int L = __ffs(m) - 1;
                    c = (lane <= L) ? val : 0;
                } else c = val;
#pragma unroll
                for (int o = 16; o > 0; o >>= 1) c += __shfl_down_sync(0xffffffffu, c, o);
                c = __shfl_sync(0xffffffffu, c, 0);
                P += c;
                if (m) break;
                i0 -= 32;
            }
            if (lane == 0) {
                stvol64(&g_scan_state[b], (2ULL << 32) | (unsigned)(P + total));
                sprefix = P;
            }
        } else if (lane == 0) sprefix = 0;
    }
    __syncthreads();
    int excl = incl - v + sprefix;
    if (i < n) {
        g_rowptr[i] = excl;
        g_pos[i] = excl;
        if (i == n - 1) g_rowptr[n] = excl + v;
    }
    // x16 conversion for this block's rows
    int base = b * SCAN_B;
    for (int idx = t; idx < SCAN_B * 16; idx += SCAN_B) {
        int row = base + (idx >> 4);
        if (row >= n) break;
        int seg = idx & 15;
        float dv = g_dinv[row];
        const float4* xp = (const float4*)(x + (size_t)row * IND + seg * 8);
        float4 a = xp[0], bb = xp[1];
        __half2 h0 = __floats2half2_rn(a.x * dv, a.y * dv);
        __half2 h1 = __floats2half2_rn(a.z * dv, a.w * dv);
        __half2 h2 = __floats2half2_rn(bb.x * dv, bb.y * dv);
        __half2 h3 = __floats2half2_rn(bb.z * dv, bb.w * dv);
        uint4 o;
        o.x = *(uint32_t*)&h0; o.y = *(uint32_t*)&h1;
        o.z = *(uint32_t*)&h2; o.w = *(uint32_t*)&h3;
        *(uint4*)(g_x16 + (size_t)row * IND + seg * 8) = o;
    }
}

__global__ void scatter4_k(const int* __restrict__ src, const int* __restrict__ dst,
                           int E4, int E) {
    int i = blockIdx.x * blockDim.x + threadIdx.x;
    if (i < E4) {
        int4 s = ((const int4*)src)[i];
        int4 d = ((const int4*)dst)[i];
        g_csr_src[atomicAdd(&g_pos[d.x], 1)] = s.x;
        g_csr_src[atomicAdd(&g_pos[d.y], 1)] = s.y;
        g_csr_src[atomicAdd(&g_pos[d.z], 1)] = s.z;
        g_csr_src[atomicAdd(&g_pos[d.w], 1)] = s.w;
    }
    if (i == 0)
        for (int k = E4 * 4; k < E; k++)
            g_csr_src[atomicAdd(&g_pos[dst[k]], 1)] = src[k];
}
__global__ void scatter_k(const int* __restrict__ src, const int* __restrict__ dst, int E) {
    int e = blockIdx.x * blockDim.x + threadIdx.x;
    if (e < E) g_csr_src[atomicAdd(&g_pos[dst[e]], 1)] = src[e];
}

// ---------------- aggregation (CSR, warp per dst, fp16 gather, HADD2 tree) ----------------
// agg16[i] = half(di * (x16[i] + sum_j x16[src_j]))
__global__ void agg1_k(int n) {
    int w = (blockIdx.x * blockDim.x + threadIdx.x) >> 5;
    if (w >= n) return;
    int c = threadIdx.x & 31;
    float di = g_dinv[w];
    float4 sum;
    {
        uint2 ps = __ldg((const uint2*)(g_x16 + (size_t)w * IND) + c);  // self
        float2 a = __half22float2(u2h(ps.x));
        float2 b = __half22float2(u2h(ps.y));
        sum = make_float4(a.x, a.y, b.x, b.y);
    }
    int j = g_rowptr[w], end = g_rowptr[w + 1];
    for (; j + 7 < end; j += 8) {
        int s0 = __ldg(&g_csr_src[j]);
        int s1 = __ldg(&g_csr_src[j + 1]);
        int s2 = __ldg(&g_csr_src[j + 2]);
        int s3 = __ldg(&g_csr_src[j + 3]);
        int s4 = __ldg(&g_csr_src[j + 4]);
        int s5 = __ldg(&g_csr_src[j + 5]);
        int s6 = __ldg(&g_csr_src[j + 6]);
        int s7 = __ldg(&g_csr_src[j + 7]);
        uint2 p0 = __ldg((const uint2*)(g_x16 + (size_t)s0 * IND) + c);
        uint2 p1 = __ldg((const uint2*)(g_x16 + (size_t)s1 * IND) + c);
        uint2 p2 = __ldg((const uint2*)(g_x16 + (size_t)s2 * IND) + c);
        uint2 p3 = __ldg((const uint2*)(g_x16 + (size_t)s3 * IND) + c);
        uint2 p4 = __ldg((const uint2*)(g_x16 + (size_t)s4 * IND) + c);
        uint2 p5 = __ldg((const uint2*)(g_x16 + (size_t)s5 * IND) + c);
        uint2 p6 = __ldg((const uint2*)(g_x16 + (size_t)s6 * IND) + c);
        uint2 p7 = __ldg((const uint2*)(g_x16 + (size_t)s7 * IND) + c);
        // HADD2 pairwise tree (3 levels), then fp32 accumulate
        __half2 qx0 = __hadd2(u2h(p0.x), u2h(p1.x));
        __half2 qx1 = __hadd2(u2h(p2.x), u2h(p3.x));
        __half2 qx2 = __hadd2(u2h(p4.x), u2h(p5.x));
        __half2 qx3 = __hadd2(u2h(p6.x), u2h(p7.x));
        __half2 rx0 = __hadd2(qx0, qx1);
        __half2 rx1 = __hadd2(qx2, qx3);
        __half2 qy0 = __hadd2(u2h(p0.y), u2h(p1.y));
        __half2 qy1 = __hadd2(u2h(p2.y), u2h(p3.y));
        __half2 qy2 = __hadd2(u2h(p4.y), u2h(p5.y));
        __half2 qy3 = __hadd2(u2h(p6.y), u2h(p7.y));
        __half2 ry0 = __hadd2(qy0, qy1);
        __half2 ry1 = __hadd2(qy2, qy3);
        float2 fx0 = __half22float2(rx0);
        float2 fx1 = __half22float2(rx1);
        float2 fy0 = __half22float2(ry0);
        float2 fy1 = __half22float2(ry1);
        sum.x += fx0.x + fx1.x;
        sum.y += fx0.y + fx1.y;
        sum.z += fy0.x + fy1.x;
        sum.w += fy0.y + fy1.y;
    }
    if (j + 3 < end) {
        int s0 = __ldg(&g_csr_src[j]);
        int s1 = __ldg(&g_csr_src[j + 1]);
        int s2 = __ldg(&g_csr_src[j + 2]);
        int s3 = __ldg(&g_csr_src[j + 3]);
        uint2 p0 = __ldg((const uint2*)(g_x16 + (size_t)s0 * IND) + c);
        uint2 p1 = __ldg((const uint2*)(g_x16 + (size_t)s1 * IND) + c);
        uint2 p2 = __ldg((const uint2*)(g_x16 + (size_t)s2 * IND) + c);
        uint2 p3 = __ldg((const uint2*)(g_x16 + (size_t)s3 * IND) + c);
        __half2 qx0 = __hadd2(u2h(p0.x), u2h(p1.x));
        __half2 qx1 = __hadd2(u2h(p2.x), u2h(p3.x));
        __half2 qy0 = __hadd2(u2h(p0.y), u2h(p1.y));
        __half2 qy1 = __hadd2(u2h(p2.y), u2h(p3.y));
        float2 fx0 = __half22float2(qx0);
        float2 fx1 = __half22float2(qx1);
        float2 fy0 = __half22float2(qy0);
        float2 fy1 = __half22float2(qy1);
        sum.x += fx0.x + fx1.x;
        sum.y += fx0.y + fx1.y;
        sum.z += fy0.x + fy1.x;
        sum.w += fy0.y + fy1.y;
        j += 4;
    }
    for (; j < end; j++) {
        int s = __ldg(&g_csr_src[j]);
        uint2 p = __ldg((const uint2*)(g_x16 + (size_t)s * IND) + c);
        float2 a = __half22float2(u2h(p.x));
        float2 b = __half22float2(u2h(p.y));
        sum.x += a.x; sum.y += a.y; sum.z += b.x; sum.w += b.y;
    }
    __half2 ha = __floats2half2_rn(sum.x * di, sum.y * di);
    __half2 hb = __floats2half2_rn(sum.z * di, sum.w * di);
    uint2 pk;
    pk.x = *(uint32_t*)&ha; pk.y = *(uint32_t*)&hb;
    *(uint2*)(g_agg16 + (size_t)w * IND + c * 4) = pk;
}

// out[i] = di * (h216[i] + sum_j h216[src_j]) + b2   (+ re-zero degc for next replay)
__global__ void agg2_k(const float* __restrict__ b2, float* __restrict__ out, int n) {
    int gi = blockIdx.x * blockDim.x + threadIdx.x;
    if (gi < n) g_degc[gi] = 0;        // restore invariant for next replay
    int w = gi >> 5;
    if (w >= n) return;
    int c = threadIdx.x & 31;
    float di = g_dinv[w];
    float2 bb = ((const float2*)b2)[c];
    float2 sum;
    {
        uint32_t p = __ldg((const uint32_t*)(g_h216 + (size_t)w * OUTD) + c);  // self
        sum = __half22float2(u2h(p));
    }
    int j = g_rowptr[w], end = g_rowptr[w + 1];
    for (; j + 7 < end; j += 8) {
        int s0 = __ldg(&g_csr_src[j]);
        int s1 = __ldg(&g_csr_src[j + 1]);
        int s2 = __ldg(&g_csr_src[j + 2]);
        int s3 = __ldg(&g_csr_src[j + 3]);
        int s4 = __ldg(&g_csr_src[j + 4]);
        int s5 = __ldg(&g_csr_src[j + 5]);
        int s6 = __ldg(&g_csr_src[j + 6]);
        int s7 = __ldg(&g_csr_src[j + 7]);
        uint32_t p0 = __ldg((const uint32_t*)(g_h216 + (size_t)s0 * OUTD) + c);
        uint32_t p1 = __ldg((const uint32_t*)(g_h216 + (size_t)s1 * OUTD) + c);
        uint32_t p2 = __ldg((const uint32_t*)(g_h216 + (size_t)s2 * OUTD) + c);
        uint32_t p3 = __ldg((const uint32_t*)(g_h216 + (size_t)s3 * OUTD) + c);
        uint32_t p4 = __ldg((const uint32_t*)(g_h216 + (size_t)s4 * OUTD) + c);
        uint32_t p5 = __ldg((const uint32_t*)(g_h216 + (size_t)s5 * OUTD) + c);
        uint32_t p6 = __ldg((const uint32_t*)(g_h216 + (size_t)s6 * OUTD) + c);
        uint32_t p7 = __ldg((const uint32_t*)(g_h216 + (size_t)s7 * OUTD) + c);
        __half2 q0 = __hadd2(u2h(p0), u2h(p1));
        __half2 q1 = __hadd2(u2h(p2), u2h(p3));
        __half2 q2 = __hadd2(u2h(p4), u2h(p5));
        __half2 q3 = __hadd2(u2h(p6), u2h(p7));
        __half2 r0 = __hadd2(q0, q1);
        __half2 r1 = __hadd2(q2, q3);
        float2 f0 = __half22float2(r0);
        float2 f1 = __half22float2(r1);
        sum.x += f0.x + f1.x;
        sum.y += f0.y + f1.y;
    }
    if (j + 3 < end) {
        int s0 = __ldg(&g_csr_src[j]);
        int s1 = __ldg(&g_csr_src[j + 1]);
        int s2 = __ldg(&g_csr_src[j + 2]);
        int s3 = __ldg(&g_csr_src[j + 3]);
        uint32_t p0 = __ldg((const uint32_t*)(g_h216 + (size_t)s0 * OUTD) + c);
        uint32_t p1 = __ldg((const uint32_t*)(g_h216 + (size_t)s1 * OUTD) + c);
        uint32_t p2 = __ldg((const uint32_t*)(g_h216 + (size_t)s2 * OUTD) + c);
        uint32_t p3 = __ldg((const uint32_t*)(g_h216 + (size_t)s3 * OUTD) + c);
        __half2 q0 = __hadd2(u2h(p0), u2h(p1));
        __half2 q1 = __hadd2(u2h(p2), u2h(p3));
        float2 f0 = __half22float2(q0);
        float2 f1 = __half22float2(q1);
        sum.x += f0.x + f1.x;
        sum.y += f0.y + f1.y;
        j += 4;
    }
    for (; j < end; j++) {
        int s = __ldg(&g_csr_src[j]);
        uint32_t p = __ldg((const uint32_t*)(g_h216 + (size_t)s * OUTD) + c);
        float2 a = __half22float2(u2h(p));
        sum.x += a.x; sum.y += a.y;
    }
    float2 o;
    o.x = sum.x * di + bb.x;
    o.y = sum.y * di + bb.y;
    ((float2*)(out + (size_t)w * OUTD))[c] = o;
}

// ---------------- W prep (merged) ----------------
__global__ void wprep_k(const float* __restrict__ W1, const float* __restrict__ W2) {
    int i = blockIdx.x * blockDim.x + threadIdx.x;
    if (i < HID * IND) {
        int nn = i & 127, k = i >> 7;
        float w = W1[k * HID + nn];
        __half hi, lo; split_h(w, hi, lo);
        g_w1hi[nn * IND + k] = hi;
        g_w1lo[nn * IND + k] = lo;
    }
    int j = i - HID * IND;
    if (j >= 0 && j < OUTD * IND) {
        int nn = j & 63, k = j >> 6;
        float w = W2[k * OUTD + nn];
        __half hi, lo; split_h(w, hi, lo);
        g_w2hi[nn * IND + k] = hi;
        g_w2lo[nn * IND + k] = lo;
    }
}

// ---------------- fused HMMA GEMM1+GEMM2 ----------------
#define LDA 136

__global__ __launch_bounds__(256, 1) void gemmf_mma(const float* __restrict__ b1, int n) {
    extern __shared__ __half sm[];
    __half* Ah  = sm;                     // 128*136 (A, then h16)
    __half* B1h = Ah + 128 * LDA;         // 128*136
    __half* B1l = B1h + 128 * LDA;
    __half* B2h = B1l + 128 * LDA;        // 64*136
    __half* B2l = B2h + 64 * LDA;
    int tid = threadIdx.x, wid = tid >> 5, lane = tid & 31;
    int r0 = blockIdx.x * 128;

    for (int i = tid; i < 2048; i += 256) {
        int row = i >> 4, seg = i & 15;
        int gr = r0 + row;
        uint4 v = (gr < n) ? ((const uint4*)(g_agg16 + (size_t)gr * IND))[seg]
                           : make_uint4(0u, 0u, 0u, 0u);
        *(uint4*)(Ah + row * LDA + seg * 8) = v;
    }
    for (int i = tid; i < 2048; i += 256) {
        int row = i >> 4, seg = i & 15;
        *(uint4*)(B1h + row * LDA + seg * 8) = ((const uint4*)g_w1hi)[i];
        *(uint4*)(B1l + row * LDA + seg * 8) = ((const uint4*)g_w1lo)[i];
    }
    for (int i = tid; i < 1024; i += 256) {
        int row = i >> 4, seg = i & 15;
        *(uint4*)(B2h + row * LDA + seg * 8) = ((const uint4*)g_w2hi)[i];
        *(uint4*)(B2l + row * LDA + seg * 8) = ((const uint4*)g_w2lo)[i];
    }
    __syncthreads();

    uint32_t ah_b = smem_u32(Ah);
    uint32_t b1h_b = smem_u32(B1h), b1l_b = smem_u32(B1l);
    uint32_t b2h_b = smem_u32(B2h), b2l_b = smem_u32(B2l);
    int a_row = wid * 16 + (lane & 15);
    int a_co = (lane >> 4) * 8;
    uint32_t a_off = (uint32_t)(a_row * LDA + a_co) * 2;
    int b_row = (lane & 7) + ((lane >> 4) << 3);
    int b_co = ((lane >> 3) & 1) * 8;
    uint32_t b_off = (uint32_t)(b_row * LDA + b_co) * 2;

    int grp = lane >> 2, qid = lane & 3;
    int rowAl = wid * 16 + grp;
    int rowBl = rowAl + 8;

    // ---- pass 1 ----
    {
        float acc[16][4];
#pragma unroll
        for (int t = 0; t < 16; t++)
#pragma unroll
            for (int j = 0; j < 4; j++) acc[t][j] = 0.f;

#pragma unroll
        for (int ks = 0; ks < 8; ks++) {
            uint32_t ahr[4];
            ldm_x4(ahr, ah_b + a_off + ks * 32);
#pragma unroll
            for (int np = 0; np < 8; np++) {
                uint32_t bhr[4], blr[4];
                uint32_t bo = b_off + (uint32_t)(np * 16 * LDA * 2) + ks * 32;
                ldm_x4(bhr, b1h_b + bo);
                ldm_x4(blr, b1l_b + bo);
                mma16816(acc[2 * np], ahr, bhr);
                mma16816(acc[2 * np], ahr, blr);
                mma16816(acc[2 * np + 1], ahr, bhr + 2);
                mma16816(acc[2 * np + 1], ahr, blr + 2);
            }
        }
#pragma unroll
        for (int t = 0; t < 16; t++) {
            int col = t * 8 + qid * 2;
            float2 bb = *(const float2*)(b1 + col);
            *(__half2*)(Ah + rowAl * LDA + col) =
                __floats2half2_rn(fmaxf(acc[t][0] + bb.x, 0.f),
                                  fmaxf(acc[t][1] + bb.y, 0.f));
            *(__half2*)(Ah + rowBl * LDA + col) =
                __floats2half2_rn(fmaxf(acc[t][2] + bb.x, 0.f),
                                  fmaxf(acc[t][3] + bb.y, 0.f));
        }
    }
    __syncwarp();

    // ---- pass 2 ----
    {
        float acc[8][4];
#pragma unroll
        for (int t = 0; t < 8; t++)
#pragma unroll
            for (int j = 0; j < 4; j++) acc[t][j] = 0.f;

#pragma unroll
        for (int ks = 0; ks < 8; ks++) {
            uint32_t ahr[4];
            ldm_x4(ahr, ah_b + a_off + ks * 32);
#pragma unroll
            for (int np = 0; np < 4; np++) {
                uint32_t bhr[4], blr[4];
                uint32_t bo = b_off + (uint32_t)(np * 16 * LDA * 2) + ks * 32;
                ldm_x4(bhr, b2h_b + bo);
                ldm_x4(blr, b2l_b + bo);
                mma16816(acc[2 * np], ahr, bhr);
                mma16816(acc[2 * np], ahr, blr);
                mma16816(acc[2 * np + 1], ahr, bhr + 2);
                mma16816(acc[2 * np + 1], ahr, blr + 2);
            }
        }
        int rowA = r0 + rowAl;
        int rowB = r0 + rowBl;
        float dva = (rowA < n) ? g_dinv[rowA] : 0.f;
        float dvb = (rowB < n) ? g_dinv[rowB] : 0.f;
#pragma unroll
        for (int t = 0; t < 8; t++) {
            int col = t * 8 + qid * 2;
            if (rowA < n)
                *(__half2*)(g_h216 + (size_t)rowA * OUTD + col) =
                    __floats2half2_rn(acc[t][0] * dva, acc[t][1] * dva);
            if (rowB < n)
                *(__half2*)(g_h216 + (size_t)rowB * OUTD + col) =
                    __floats2half2_rn(acc[t][2] * dvb, acc[t][3] * dvb);
        }
    }
}

// ---------------- launch ----------------
extern "C" void kernel_launch(void* const* d_in, const int* in_sizes, int n_in,
                              void* d_out, int out_size) {
    const float* x  = (const float*)d_in[0];
    const int*   ei = (const int*)d_in[1];
    const float* W1 = (const float*)d_in[2];
    const float* b1 = (const float*)d_in[3];
    const float* W2 = (const float*)d_in[4];
    const float* b2 = (const float*)d_in[5];
    float* out      = (float*)d_out;

    int n = in_sizes[0] / IND;
    int E = in_sizes[1] / 2;
    const int* src = ei;
    const int* dst = ei + E;

    const int SMF = 3 * (128 * LDA * 2) + 2 * (64 * LDA * 2);  // 139264
    cudaFuncSetAttribute(gemmf_mma, cudaFuncAttributeMaxDynamicSharedMemorySize, SMF);

    const int TB = 256;
    int nb = (n + SCAN_B - 1) / SCAN_B;   // 98 <= 148: lookback co-residency holds
    int gblk = (n + 127) / 128;
    bool vec4 = (E % 4 == 0) && ((((uintptr_t)dst) & 15) == 0) && ((((uintptr_t)src) & 15) == 0);

    if (vec4) deg4_k<<<(E / 4 + TB - 1) / TB, TB>>>(dst, E / 4, E);
    else      deg_k<<<(E + TB - 1) / TB, TB>>>(dst, E);
    scanx_k<<<nb, SCAN_B>>>(x, n);
    if (vec4) scatter4_k<<<(E / 4 + TB - 1) / TB, TB>>>(src, dst, E / 4, E);
    else      scatter_k<<<(E + TB - 1) / TB, TB>>>(src, dst, E);

    int aggBlocks = (int)(((long long)n * 32 + TB - 1) / TB);
    agg1_k<<<aggBlocks, TB>>>(n);
    wprep_k<<<((HID + OUTD) * IND + TB - 1) / TB, TB>>>(W1, W2);
    gemmf_mma<<<gblk, TB, SMF>>>(b1, n);
    agg2_k<<<aggBlocks, TB>>>(b2, out, n);
}

// round 13
// speedup vs baseline: 1.0224x; 1.0224x over previous
#include <cuda_runtime.h>
#include <cuda_fp16.h>
#include <cstdint>

#define NMAX 100000
#define EMAX 1600000
#define IND 128
#define HID 128
#define OUTD 64
#define SCAN_B 1024
#define MAXBLK 128

// ---------------- scratch (static __device__, allocation-free) ----------------
__device__ int   g_degc[NMAX];
__device__ float g_dinv[NMAX];
__device__ int   g_rowptr[NMAX + 1];
__device__ int   g_pos[NMAX];
__device__ int   g_csr_off[EMAX];               // src byte-offset into g_x16 (src*256)
__device__ unsigned long long g_scan_state[MAXBLK];  // (flag<<32)|value; 0=invalid,1=agg,2=prefix
__device__ __half g_x16[(size_t)NMAX * IND];    // x * dinv, f16 (gather table L1)
__device__ __half g_agg16[(size_t)NMAX * IND];  // layer-1 aggregate, f16 (GEMM A)
__device__ __half g_h216[(size_t)NMAX * OUTD];  // h2 * dinv, f16 (gather table L2)
// W pre-transposed to [n][k] f16 hi/lo (hi + lo == fp32 weight to ~2^-22)
__device__ __half g_w1hi[HID * IND];
__device__ __half g_w1lo[HID * IND];
__device__ __half g_w2hi[OUTD * IND];
__device__ __half g_w2lo[OUTD * IND];

__device__ __forceinline__ uint32_t smem_u32(const void* p) {
    uint32_t a;
    asm("{ .reg .u64 t; cvta.to.shared.u64 t, %1; cvt.u32.u64 %0, t; }" : "=r"(a) : "l"(p));
    return a;
}
__device__ __forceinline__ void ldm_x4(uint32_t* r, uint32_t addr) {
    asm volatile("ldmatrix.sync.aligned.m8n8.x4.shared.b16 {%0,%1,%2,%3}, [%4];"
                 : "=r"(r[0]), "=r"(r[1]), "=r"(r[2]), "=r"(r[3]) : "r"(addr));
}
__device__ __forceinline__ void mma16816(float* d, const uint32_t* a, const uint32_t* b) {
    asm volatile(
        "mma.sync.aligned.m16n8k16.row.col.f32.f16.f16.f32 "
        "{%0,%1,%2,%3}, {%4,%5,%6,%7}, {%8,%9}, {%0,%1,%2,%3};"
        : "+f"(d[0]), "+f"(d[1]), "+f"(d[2]), "+f"(d[3])
        : "r"(a[0]), "r"(a[1]), "r"(a[2]), "r"(a[3]), "r"(b[0]), "r"(b[1]));
}
__device__ __forceinline__ void split_h(float v, __half& hi, __half& lo) {
    hi = __float2half_rn(v);
    lo = __float2half_rn(v - __half2float(hi));
}
__device__ __forceinline__ unsigned long long ldvol64(const unsigned long long* p) {
    unsigned long long v;
    asm volatile("ld.volatile.global.u64 %0, [%1];" : "=l"(v) : "l"(p));
    return v;
}
__device__ __forceinline__ void stvol64(unsigned long long* p, unsigned long long v) {
    asm volatile("st.volatile.global.u64 [%0], %1;" :: "l"(p), "l"(v));
}

// ---------------- CSR build ----------------
// NOTE: g_degc is zeroed by agg2_k at the end of each replay (and statically for call 1).
__global__ void deg4_k(const int* __restrict__ dst, int E4, int E) {
    int i = blockIdx.x * blockDim.x + threadIdx.x;
    if (i < MAXBLK) g_scan_state[i] = 0ULL;   // reset lookback state for this replay
    if (i < E4) {
        int4 d = ((const int4*)dst)[i];
        atomicAdd(&g_degc[d.x], 1);
        atomicAdd(&g_degc[d.y], 1);
        atomicAdd(&g_degc[d.z], 1);
        atomicAdd(&g_degc[d.w], 1);
    }
    if (i == 0)
        for (int k = E4 * 4; k < E; k++) atomicAdd(&g_degc[dst[k]], 1);
}
__global__ void deg_k(const int* __restrict__ dst, int E) {
    int i = blockIdx.x * blockDim.x + threadIdx.x;
    if (i < MAXBLK) g_scan_state[i] = 0ULL;
    if (i < E) atomicAdd(&g_degc[dst[i]], 1);
}

// Single-kernel exclusive scan (decoupled lookback) + dinv + x16 conversion.
// Grid must be <= 148 blocks (co-residency). Block b owns rows [b*1024, b*1024+1024).
__global__ __launch_bounds__(SCAN_B) void scanx_k(const float* __restrict__ x, int n) {
    __shared__ int wsum[32];
    __shared__ int sprefix;
    int b = blockIdx.x, t = threadIdx.x;
    int i = b * SCAN_B + t;
    int v = (i < n) ? g_degc[i] : 0;
    if (i < n) g_dinv[i] = rsqrtf((float)v + 1.0f);
    int lane = t & 31, w = t >> 5;
    int x_ = v;
#pragma unroll
    for (int o = 1; o < 32; o <<= 1) {
        int y = __shfl_up_sync(0xffffffffu, x_, o);
        if (lane >= o) x_ += y;
    }
    if (lane == 31) wsum[w] = x_;
    __syncthreads();
    if (w == 0) {
        int s = wsum[lane];
#pragma unroll
        for (int o = 1; o < 32; o <<= 1) {
            int y = __shfl_up_sync(0xffffffffu, s, o);
            if (lane >= o) s += y;
        }
        wsum[lane] = s;
    }
    __syncthreads();
    int incl = x_ + (w > 0 ? wsum[w - 1] : 0);
    int total = wsum[31];

    if (w == 0) {
        if (lane == 0)
            stvol64(&g_scan_state[b],
                    ((unsigned long long)((b == 0) ? 2u : 1u) << 32) | (unsigned)total);
        __syncwarp();
        if (b > 0) {
            int P = 0;
            int i0 = b - 1;
            while (true) {
                int ii = i0 - lane;
                unsigned long long s = (ii >= 0) ? ldvol64(&g_scan_state[ii])
                                                 : (2ULL << 32);
                while (__any_sync(0xffffffffu, (s >> 32) == 0))
                    if ((s >> 32) == 0) s = ldvol64(&g_scan_state[ii]);
                int f = (int)(s >> 32);
                int val = (int)(unsigned)s;
                unsigned m = __ballot_sync(0xffffffffu, f == 2);
                int c;
                if (m) {
                    int L = __ffs(m) - 1;
                    c = (lane <= L) ? val : 0;
                } else c = val;
#pragma unroll
                for (int o = 16; o > 0; o >>= 1) c += __shfl_down_sync(0xffffffffu, c, o);
                c = __shfl_sync(0xffffffffu, c, 0);
                P += c;
                if (m) break;
                i0 -= 32;
            }
            if (lane == 0) {
                stvol64(&g_scan_state[b], (2ULL << 32) | (unsigned)(P + total));
                sprefix = P;
            }
        } else if (lane == 0) sprefix = 0;
    }
    __syncthreads();
    int excl = incl - v + sprefix;
    if (i < n) {
        g_rowptr[i] = excl;
        g_pos[i] = excl;
        if (i == n - 1) g_rowptr[n] = excl + v;
    }
    // x16 conversion for this block's rows
    int base = b * SCAN_B;
    for (int idx = t; idx < SCAN_B * 16; idx += SCAN_B) {
        int row = base + (idx >> 4);
        if (row >= n) break;
        int seg = idx & 15;
        float dv = g_dinv[row];
        const float4* xp = (const float4*)(x + (size_t)row * IND + seg * 8);
        float4 a = xp[0], bb = xp[1];
        __half2 h0 = __floats2half2_rn(a.x * dv, a.y * dv);
        __half2 h1 = __floats2half2_rn(a.z * dv, a.w * dv);
        __half2 h2 = __floats2half2_rn(bb.x * dv, bb.y * dv);
        __half2 h3 = __floats2half2_rn(bb.z * dv, bb.w * dv);
        uint4 o;
        o.x = *(uint32_t*)&h0; o.y = *(uint32_t*)&h1;
        o.z = *(uint32_t*)&h2; o.w = *(uint32_t*)&h3;
        *(uint4*)(g_x16 + (size_t)row * IND + seg * 8) = o;
    }
}

// Scatter: store BYTE OFFSET into g_x16 (src * 256); agg2 derives its 128B offset via >>1.
__global__ void scatter4_k(const int* __restrict__ src, const int* __restrict__ dst,
                           int E4, int E) {
    int i = blockIdx.x * blockDim.x + threadIdx.x;
    if (i < E4) {
        int4 s = ((const int4*)src)[i];
        int4 d = ((const int4*)dst)[i];
        g_csr_off[atomicAdd(&g_pos[d.x], 1)] = s.x << 8;
        g_csr_off[atomicAdd(&g_pos[d.y], 1)] = s.y << 8;
        g_csr_off[atomicAdd(&g_pos[d.z], 1)] = s.z << 8;
        g_csr_off[atomicAdd(&g_pos[d.w], 1)] = s.w << 8;
    }
    if (i == 0)
        for (int k = E4 * 4; k < E; k++)
            g_csr_off[atomicAdd(&g_pos[dst[k]], 1)] = src[k] << 8;
}
__global__ void scatter_k(const int* __restrict__ src, const int* __restrict__ dst, int E) {
    int e = blockIdx.x * blockDim.x + threadIdx.x;
    if (e < E) g_csr_off[atomicAdd(&g_pos[dst[e]], 1)] = src[e] << 8;
}

// ---------------- aggregation (CSR, warp per dst, fp16 gather, 8-way MLP) ----------------
__device__ __forceinline__ void acc_x16(float4& sum, uint2 p) {
    float2 a = __half22float2(*(__half2*)&p.x);
    float2 b = __half22float2(*(__half2*)&p.y);
    sum.x += a.x; sum.y += a.y; sum.z += b.x; sum.w += b.y;
}
__device__ __forceinline__ uint2 gx16(int byteoff, int c) {
    return __ldg((const uint2*)((const char*)g_x16 + byteoff) + c);
}
__device__ __forceinline__ uint32_t gh216(int byteoff, int c) {
    return __ldg((const uint32_t*)((const char*)g_h216 + (byteoff >> 1)) + c);
}

// agg16[i] = half(di * (x16[i] + sum_j x16[src_j]))
__global__ void agg1_k(int n) {
    int w = (blockIdx.x * blockDim.x + threadIdx.x) >> 5;
    if (w >= n) return;
    int c = threadIdx.x & 31;
    float di = g_dinv[w];
    float4 sum = make_float4(0.f, 0.f, 0.f, 0.f);
    acc_x16(sum, __ldg((const uint2*)(g_x16 + (size_t)w * IND) + c));  // self
    int j = g_rowptr[w], end = g_rowptr[w + 1];
    for (; j + 7 < end; j += 8) {
        int s0 = __ldg(&g_csr_off[j]);
        int s1 = __ldg(&g_csr_off[j + 1]);
        int s2 = __ldg(&g_csr_off[j + 2]);
        int s3 = __ldg(&g_csr_off[j + 3]);
        int s4 = __ldg(&g_csr_off[j + 4]);
        int s5 = __ldg(&g_csr_off[j + 5]);
        int s6 = __ldg(&g_csr_off[j + 6]);
        int s7 = __ldg(&g_csr_off[j + 7]);
        uint2 p0 = gx16(s0, c);
        uint2 p1 = gx16(s1, c);
        uint2 p2 = gx16(s2, c);
        uint2 p3 = gx16(s3, c);
        uint2 p4 = gx16(s4, c);
        uint2 p5 = gx16(s5, c);
        uint2 p6 = gx16(s6, c);
        uint2 p7 = gx16(s7, c);
        acc_x16(sum, p0); acc_x16(sum, p1); acc_x16(sum, p2); acc_x16(sum, p3);
        acc_x16(sum, p4); acc_x16(sum, p5); acc_x16(sum, p6); acc_x16(sum, p7);
    }
    if (j + 3 < end) {
        int s0 = __ldg(&g_csr_off[j]);
        int s1 = __ldg(&g_csr_off[j + 1]);
        int s2 = __ldg(&g_csr_off[j + 2]);
        int s3 = __ldg(&g_csr_off[j + 3]);
        uint2 p0 = gx16(s0, c);
        uint2 p1 = gx16(s1, c);
        uint2 p2 = gx16(s2, c);
        uint2 p3 = gx16(s3, c);
        acc_x16(sum, p0); acc_x16(sum, p1); acc_x16(sum, p2); acc_x16(sum, p3);
        j += 4;
    }
    for (; j < end; j++) {
        int s = __ldg(&g_csr_off[j]);
        acc_x16(sum, gx16(s, c));
    }
    __half2 ha = __floats2half2_rn(sum.x * di, sum.y * di);
    __half2 hb = __floats2half2_rn(sum.z * di, sum.w * di);
    uint2 pk;
    pk.x = *(uint32_t*)&ha; pk.y = *(uint32_t*)&hb;
    *(uint2*)(g_agg16 + (size_t)w * IND + c * 4) = pk;
}

// out[i] = di * (h216[i] + sum_j h216[src_j]) + b2   (+ re-zero degc for next replay)
__global__ void agg2_k(const float* __restrict__ b2, float* __restrict__ out, int n) {
    int gi = blockIdx.x * blockDim.x + threadIdx.x;
    if (gi < n) g_degc[gi] = 0;        // restore invariant for next replay
    int w = gi >> 5;
    if (w >= n) return;
    int c = threadIdx.x & 31;
    float di = g_dinv[w];
    float2 bb = ((const float2*)b2)[c];
    float2 sum;
    {
        uint32_t p = __ldg((const uint32_t*)(g_h216 + (size_t)w * OUTD) + c);  // self
        sum = __half22float2(*(__half2*)&p);
    }
    int j = g_rowptr[w], end = g_rowptr[w + 1];
    for (; j + 7 < end; j += 8) {
        int s0 = __ldg(&g_csr_off[j]);
        int s1 = __ldg(&g_csr_off[j + 1]);
        int s2 = __ldg(&g_csr_off[j + 2]);
        int s3 = __ldg(&g_csr_off[j + 3]);
        int s4 = __ldg(&g_csr_off[j + 4]);
        int s5 = __ldg(&g_csr_off[j + 5]);
        int s6 = __ldg(&g_csr_off[j + 6]);
        int s7 = __ldg(&g_csr_off[j + 7]);
        uint32_t p0 = gh216(s0, c);
        uint32_t p1 = gh216(s1, c);
        uint32_t p2 = gh216(s2, c);
        uint32_t p3 = gh216(s3, c);
        uint32_t p4 = gh216(s4, c);
        uint32_t p5 = gh216(s5, c);
        uint32_t p6 = gh216(s6, c);
        uint32_t p7 = gh216(s7, c);
        float2 a0 = __half22float2(*(__half2*)&p0);
        float2 a1 = __half22float2(*(__half2*)&p1);
        float2 a2 = __half22float2(*(__half2*)&p2);
        float2 a3 = __half22float2(*(__half2*)&p3);
        float2 a4 = __half22float2(*(__half2*)&p4);
        float2 a5 = __half22float2(*(__half2*)&p5);
        float2 a6 = __half22float2(*(__half2*)&p6);
        float2 a7 = __half22float2(*(__half2*)&p7);
        sum.x += ((a0.x + a1.x) + (a2.x + a3.x)) + ((a4.x + a5.x) + (a6.x + a7.x));
        sum.y += ((a0.y + a1.y) + (a2.y + a3.y)) + ((a4.y + a5.y) + (a6.y + a7.y));
    }
    if (j + 3 < end) {
        int s0 = __ldg(&g_csr_off[j]);
        int s1 = __ldg(&g_csr_off[j + 1]);
        int s2 = __ldg(&g_csr_off[j + 2]);
        int s3 = __ldg(&g_csr_off[j + 3]);
        uint32_t p0 = gh216(s0, c);
        uint32_t p1 = gh216(s1, c);
        uint32_t p2 = gh216(s2, c);
        uint32_t p3 = gh216(s3, c);
        float2 a0 = __half22float2(*(__half2*)&p0);
        float2 a1 = __half22float2(*(__half2*)&p1);
        float2 a2 = __half22float2(*(__half2*)&p2);
        float2 a3 = __half22float2(*(__half2*)&p3);
        sum.x += (a0.x + a1.x) + (a2.x + a3.x);
        sum.y += (a0.y + a1.y) + (a2.y + a3.y);
        j += 4;
    }
    for (; j < end; j++) {
        int s = __ldg(&g_csr_off[j]);
        uint32_t p = gh216(s, c);
        float2 a = __half22float2(*(__half2*)&p);
        sum.x += a.x; sum.y += a.y;
    }
    float2 o;
    o.x = sum.x * di + bb.x;
    o.y = sum.y * di + bb.y;
    ((float2*)(out + (size_t)w * OUTD))[c] = o;
}

// ---------------- W prep (merged) ----------------
__global__ void wprep_k(const float* __restrict__ W1, const float* __restrict__ W2) {
    int i = blockIdx.x * blockDim.x + threadIdx.x;
    if (i < HID * IND) {
        int nn = i & 127, k = i >> 7;
        float w = W1[k * HID + nn];
        __half hi, lo; split_h(w, hi, lo);
        g_w1hi[nn * IND + k] = hi;
        g_w1lo[nn * IND + k] = lo;
    }
    int j = i - HID * IND;
    if (j >= 0 && j < OUTD * IND) {
        int nn = j & 63, k = j >> 6;
        float w = W2[k * OUTD + nn];
        __half hi, lo; split_h(w, hi, lo);
        g_w2hi[nn * IND + k] = hi;
        g_w2lo[nn * IND + k] = lo;
    }
}

// ---------------- fused HMMA GEMM1+GEMM2 ----------------
#define LDA 136

__global__ __launch_bounds__(256, 1) void gemmf_mma(const float* __restrict__ b1, int n) {
    extern __shared__ __half sm[];
    __half* Ah  = sm;                     // 128*136 (A, then h16)
    __half* B1h = Ah + 128 * LDA;         // 128*136
    __half* B1l = B1h + 128 * LDA;
    __half* B2h = B1l + 128 * LDA;        // 64*136
    __half* B2l = B2h + 64 * LDA;
    int tid = threadIdx.x, wid = tid >> 5, lane = tid & 31;
    int r0 = blockIdx.x * 128;

    for (int i = tid; i < 2048; i += 256) {
        int row = i >> 4, seg = i & 15;
        int gr = r0 + row;
        uint4 v = (gr < n) ? ((const uint4*)(g_agg16 + (size_t)gr * IND))[seg]
                           : make_uint4(0u, 0u, 0u, 0u);
        *(uint4*)(Ah + row * LDA + seg * 8) = v;
    }
    for (int i = tid; i < 2048; i += 256) {
        int row = i >> 4, seg = i & 15;
        *(uint4*)(B1h + row * LDA + seg * 8) = ((const uint4*)g_w1hi)[i];
        *(uint4*)(B1l + row * LDA + seg * 8) = ((const uint4*)g_w1lo)[i];
    }
    for (int i = tid; i < 1024; i += 256) {
        int row = i >> 4, seg = i & 15;
        *(uint4*)(B2h + row * LDA + seg * 8) = ((const uint4*)g_w2hi)[i];
        *(uint4*)(B2l + row * LDA + seg * 8) = ((const uint4*)g_w2lo)[i];
    }
    __syncthreads();

    uint32_t ah_b = smem_u32(Ah);
    uint32_t b1h_b = smem_u32(B1h), b1l_b = smem_u32(B1l);
    uint32_t b2h_b = smem_u32(B2h), b2l_b = smem_u32(B2l);
    int a_row = wid * 16 + (lane & 15);
    int a_co = (lane >> 4) * 8;
    uint32_t a_off = (uint32_t)(a_row * LDA + a_co) * 2;
    int b_row = (lane & 7) + ((lane >> 4) << 3);
    int b_co = ((lane >> 3) & 1) * 8;
    uint32_t b_off = (uint32_t)(b_row * LDA + b_co) * 2;

    int grp = lane >> 2, qid = lane & 3;
    int rowAl = wid * 16 + grp;
    int rowBl = rowAl + 8;

    // ---- pass 1 ----
    {
        float acc[16][4];
#pragma unroll
        for (int t = 0; t < 16; t++)
#pragma unroll
            for (int j = 0; j < 4; j++) acc[t][j] = 0.f;

#pragma unroll
        for (int ks = 0; ks < 8; ks++) {
            uint32_t ahr[4];
            ldm_x4(ahr, ah_b + a_off + ks * 32);
#pragma unroll
            for (int np = 0; np < 8; np++) {
                uint32_t bhr[4], blr[4];
                uint32_t bo = b_off + (uint32_t)(np * 16 * LDA * 2) + ks * 32;
                ldm_x4(bhr, b1h_b + bo);
                ldm_x4(blr, b1l_b + bo);
                mma16816(acc[2 * np], ahr, bhr);
                mma16816(acc[2 * np], ahr, blr);
                mma16816(acc[2 * np + 1], ahr, bhr + 2);
                mma16816(acc[2 * np + 1], ahr, blr + 2);
            }
        }
#pragma unroll
        for (int t = 0; t < 16; t++) {
            int col = t * 8 + qid * 2;
            float2 bb = *(const float2*)(b1 + col);
            *(__half2*)(Ah + rowAl * LDA + col) =
                __floats2half2_rn(fmaxf(acc[t][0] + bb.x, 0.f),
                                  fmaxf(acc[t][1] + bb.y, 0.f));
            *(__half2*)(Ah + rowBl * LDA + col) =
                __floats2half2_rn(fmaxf(acc[t][2] + bb.x, 0.f),
                                  fmaxf(acc[t][3] + bb.y, 0.f));
        }
    }
    __syncwarp();

    // ---- pass 2 ----
    {
        float acc[8][4];
#pragma unroll
        for (int t = 0; t < 8; t++)
#pragma unroll
            for (int j = 0; j < 4; j++) acc[t][j] = 0.f;

#pragma unroll
        for (int ks = 0; ks < 8; ks++) {
            uint32_t ahr[4];
            ldm_x4(ahr, ah_b + a_off + ks * 32);
#pragma unroll
            for (int np = 0; np < 4; np++) {
                uint32_t bhr[4], blr[4];
                uint32_t bo = b_off + (uint32_t)(np * 16 * LDA * 2) + ks * 32;
                ldm_x4(bhr, b2h_b + bo);
                ldm_x4(blr, b2l_b + bo);
                mma16816(acc[2 * np], ahr, bhr);
                mma16816(acc[2 * np], ahr, blr);
                mma16816(acc[2 * np + 1], ahr, bhr + 2);
                mma16816(acc[2 * np + 1], ahr, blr + 2);
            }
        }
        int rowA = r0 + rowAl;
        int rowB = r0 + rowBl;
        float dva = (rowA < n) ? g_dinv[rowA] : 0.f;
        float dvb = (rowB < n) ? g_dinv[rowB] : 0.f;
#pragma unroll
        for (int t = 0; t < 8; t++) {
            int col = t * 8 + qid * 2;
            if (rowA < n)
                *(__half2*)(g_h216 + (size_t)rowA * OUTD + col) =
                    __floats2half2_rn(acc[t][0] * dva, acc[t][1] * dva);
            if (rowB < n)
                *(__half2*)(g_h216 + (size_t)rowB * OUTD + col) =
                    __floats2half2_rn(acc[t][2] * dvb, acc[t][3] * dvb);
        }
    }
}

// ---------------- launch ----------------
extern "C" void kernel_launch(void* const* d_in, const int* in_sizes, int n_in,
                              void* d_out, int out_size) {
    const float* x  = (const float*)d_in[0];
    const int*   ei = (const int*)d_in[1];
    const float* W1 = (const float*)d_in[2];
    const float* b1 = (const float*)d_in[3];
    const float* W2 = (const float*)d_in[4];
    const float* b2 = (const float*)d_in[5];
    float* out      = (float*)d_out;

    int n = in_sizes[0] / IND;
    int E = in_sizes[1] / 2;
    const int* src = ei;
    const int* dst = ei + E;

    const int SMF = 3 * (128 * LDA * 2) + 2 * (64 * LDA * 2);  // 139264
    cudaFuncSetAttribute(gemmf_mma, cudaFuncAttributeMaxDynamicSharedMemorySize, SMF);

    const int TB = 256;
    int nb = (n + SCAN_B - 1) / SCAN_B;   // 98 <= 148: lookback co-residency holds
    int gblk = (n + 127) / 128;
    bool vec4 = (E % 4 == 0) && ((((uintptr_t)dst) & 15) == 0) && ((((uintptr_t)src) & 15) == 0);

    if (vec4) deg4_k<<<(E / 4 + TB - 1) / TB, TB>>>(dst, E / 4, E);
    else      deg_k<<<(E + TB - 1) / TB, TB>>>(dst, E);
    scanx_k<<<nb, SCAN_B>>>(x, n);
    if (vec4) scatter4_k<<<(E / 4 + TB - 1) / TB, TB>>>(src, dst, E / 4, E);
    else      scatter_k<<<(E + TB - 1) / TB, TB>>>(src, dst, E);

    int aggBlocks = (int)(((long long)n * 32 + TB - 1) / TB);
    agg1_k<<<aggBlocks, TB>>>(n);
    wprep_k<<<((HID + OUTD) * IND + TB - 1) / TB, TB>>>(W1, W2);
    gemmf_mma<<<gblk, TB, SMF>>>(b1, n);
    agg2_k<<<aggBlocks, TB>>>(b2, out, n);
}

// round 14
// speedup vs baseline: 1.2353x; 1.2083x over previous
#include <cuda_runtime.h>
#include <cuda_fp16.h>
#include <cstdint>

#define NMAX 100000
#define EMAX 1600000
#define IND 128
#define HID 128
#define OUTD 64
#define SCAN_B 1024
#define MAXBLK 128

// ---------------- scratch (static __device__, allocation-free) ----------------
__device__ int   g_degc[NMAX];
__device__ float g_dinv[NMAX];
__device__ int   g_rowptr[NMAX + 1];
__device__ int   g_pos[NMAX];
__device__ int   g_csr_off[EMAX];               // src byte-offset into g_x16 (src*256)
__device__ unsigned long long g_scan_state[MAXBLK];  // (flag<<32)|value; 0=invalid,1=agg,2=prefix
__device__ __half g_x16[(size_t)NMAX * IND];    // x * dinv, f16 (gather table L1)
__device__ __half g_agg16[(size_t)NMAX * IND];  // layer-1 aggregate, f16 (GEMM A)
__device__ __half g_h216[(size_t)NMAX * OUTD];  // h2 * dinv, f16 (gather table L2)
// W pre-transposed to [n][k], single f16 (rn-rounded)
__device__ __half g_w1[HID * IND];
__device__ __half g_w2[OUTD * IND];

__device__ __forceinline__ uint32_t smem_u32(const void* p) {
    uint32_t a;
    asm("{ .reg .u64 t; cvta.to.shared.u64 t, %1; cvt.u32.u64 %0, t; }" : "=r"(a) : "l"(p));
    return a;
}
__device__ __forceinline__ void ldm_x4(uint32_t* r, uint32_t addr) {
    asm volatile("ldmatrix.sync.aligned.m8n8.x4.shared.b16 {%0,%1,%2,%3}, [%4];"
                 : "=r"(r[0]), "=r"(r[1]), "=r"(r[2]), "=r"(r[3]) : "r"(addr));
}
__device__ __forceinline__ void mma16816(float* d, const uint32_t* a, const uint32_t* b) {
    asm volatile(
        "mma.sync.aligned.m16n8k16.row.col.f32.f16.f16.f32 "
        "{%0,%1,%2,%3}, {%4,%5,%6,%7}, {%8,%9}, {%0,%1,%2,%3};"
        : "+f"(d[0]), "+f"(d[1]), "+f"(d[2]), "+f"(d[3])
        : "r"(a[0]), "r"(a[1]), "r"(a[2]), "r"(a[3]), "r"(b[0]), "r"(b[1]));
}
__device__ __forceinline__ unsigned long long ldvol64(const unsigned long long* p) {
    unsigned long long v;
    asm volatile("ld.volatile.global.u64 %0, [%1];" : "=l"(v) : "l"(p));
    return v;
}
__device__ __forceinline__ void stvol64(unsigned long long* p, unsigned long long v) {
    asm volatile("st.volatile.global.u64 [%0], %1;" :: "l"(p), "l"(v));
}

// ---------------- CSR build ----------------
// NOTE: g_degc is zeroed by agg2_k at the end of each replay (and statically for call 1).
__global__ void deg4_k(const int* __restrict__ dst, int E4, int E) {
    int i = blockIdx.x * blockDim.x + threadIdx.x;
    if (i < MAXBLK) g_scan_state[i] = 0ULL;   // reset lookback state for this replay
    if (i < E4) {
        int4 d = ((const int4*)dst)[i];
        atomicAdd(&g_degc[d.x], 1);
        atomicAdd(&g_degc[d.y], 1);
        atomicAdd(&g_degc[d.z], 1);
        atomicAdd(&g_degc[d.w], 1);
    }
    if (i == 0)
        for (int k = E4 * 4; k < E; k++) atomicAdd(&g_degc[dst[k]], 1);
}
__global__ void deg_k(const int* __restrict__ dst, int E) {
    int i = blockIdx.x * blockDim.x + threadIdx.x;
    if (i < MAXBLK) g_scan_state[i] = 0ULL;
    if (i < E) atomicAdd(&g_degc[dst[i]], 1);
}

// Single-kernel exclusive scan (decoupled lookback) + dinv + x16 conversion.
// Grid must be <= 148 blocks (co-residency). Block b owns rows [b*1024, b*1024+1024).
__global__ __launch_bounds__(SCAN_B) void scanx_k(const float* __restrict__ x, int n) {
    __shared__ int wsum[32];
    __shared__ int sprefix;
    int b = blockIdx.x, t = threadIdx.x;
    int i = b * SCAN_B + t;
    int v = (i < n) ? g_degc[i] : 0;
    if (i < n) g_dinv[i] = rsqrtf((float)v + 1.0f);
    int lane = t & 31, w = t >> 5;
    int x_ = v;
#pragma unroll
    for (int o = 1; o < 32; o <<= 1) {
        int y = __shfl_up_sync(0xffffffffu, x_, o);
        if (lane >= o) x_ += y;
    }
    if (lane == 31) wsum[w] = x_;
    __syncthreads();
    if (w == 0) {
        int s = wsum[lane];
#pragma unroll
        for (int o = 1; o < 32; o <<= 1) {
            int y = __shfl_up_sync(0xffffffffu, s, o);
            if (lane >= o) s += y;
        }
        wsum[lane] = s;
    }
    __syncthreads();
    int incl = x_ + (w > 0 ? wsum[w - 1] : 0);
    int total = wsum[31];

    if (w == 0) {
        if (lane == 0)
            stvol64(&g_scan_state[b],
                    ((unsigned long long)((b == 0) ? 2u : 1u) << 32) | (unsigned)total);
        __syncwarp();
        if (b > 0) {
            int P = 0;
            int i0 = b - 1;
            while (true) {
                int ii = i0 - lane;
                unsigned long long s = (ii >= 0) ? ldvol64(&g_scan_state[ii])
                                                 : (2ULL << 32);
                while (__any_sync(0xffffffffu, (s >> 32) == 0))
                    if ((s >> 32) == 0) s = ldvol64(&g_scan_state[ii]);
                int f = (int)(s >> 32);
                int val = (int)(unsigned)s;
                unsigned m = __ballot_sync(0xffffffffu, f == 2);
                int c;
                if (m) {
                    int L = __ffs(m) - 1;
                    c = (lane <= L) ? val : 0;
                } else c = val;
#pragma unroll
                for (int o = 16; o > 0; o >>= 1) c += __shfl_down_sync(0xffffffffu, c, o);
                c = __shfl_sync(0xffffffffu, c, 0);
                P += c;
                if (m) break;
                i0 -= 32;
            }
            if (lane == 0) {
                stvol64(&g_scan_state[b], (2ULL << 32) | (unsigned)(P + total));
                sprefix = P;
            }
        } else if (lane == 0) sprefix = 0;
    }
    __syncthreads();
    int excl = incl - v + sprefix;
    if (i < n) {
        g_rowptr[i] = excl;
        g_pos[i] = excl;
        if (i == n - 1) g_rowptr[n] = excl + v;
    }
    // x16 conversion for this block's rows
    int base = b * SCAN_B;
    for (int idx = t; idx < SCAN_B * 16; idx += SCAN_B) {
        int row = base + (idx >> 4);
        if (row >= n) break;
        int seg = idx & 15;
        float dv = g_dinv[row];
        const float4* xp = (const float4*)(x + (size_t)row * IND + seg * 8);
        float4 a = xp[0], bb = xp[1];
        __half2 h0 = __floats2half2_rn(a.x * dv, a.y * dv);
        __half2 h1 = __floats2half2_rn(a.z * dv, a.w * dv);
        __half2 h2 = __floats2half2_rn(bb.x * dv, bb.y * dv);
        __half2 h3 = __floats2half2_rn(bb.z * dv, bb.w * dv);
        uint4 o;
        o.x = *(uint32_t*)&h0; o.y = *(uint32_t*)&h1;
        o.z = *(uint32_t*)&h2; o.w = *(uint32_t*)&h3;
        *(uint4*)(g_x16 + (size_t)row * IND + seg * 8) = o;
    }
}

// Scatter: store BYTE OFFSET into g_x16 (src * 256); agg2 derives its 128B offset via >>1.
__global__ void scatter4_k(const int* __restrict__ src, const int* __restrict__ dst,
                           int E4, int E) {
    int i = blockIdx.x * blockDim.x + threadIdx.x;
    if (i < E4) {
        int4 s = ((const int4*)src)[i];
        int4 d = ((const int4*)dst)[i];
        g_csr_off[atomicAdd(&g_pos[d.x], 1)] = s.x << 8;
        g_csr_off[atomicAdd(&g_pos[d.y], 1)] = s.y << 8;
        g_csr_off[atomicAdd(&g_pos[d.z], 1)] = s.z << 8;
        g_csr_off[atomicAdd(&g_pos[d.w], 1)] = s.w << 8;
    }
    if (i == 0)
        for (int k = E4 * 4; k < E; k++)
            g_csr_off[atomicAdd(&g_pos[dst[k]], 1)] = src[k] << 8;
}
__global__ void scatter_k(const int* __restrict__ src, const int* __restrict__ dst, int E) {
    int e = blockIdx.x * blockDim.x + threadIdx.x;
    if (e < E) g_csr_off[atomicAdd(&g_pos[dst[e]], 1)] = src[e] << 8;
}

// ---------------- aggregation (CSR, warp per dst, fp16 gather, 8-way MLP) ----------------
__device__ __forceinline__ void acc_x16(float4& sum, uint2 p) {
    float2 a = __half22float2(*(__half2*)&p.x);
    float2 b = __half22float2(*(__half2*)&p.y);
    sum.x += a.x; sum.y += a.y; sum.z += b.x; sum.w += b.y;
}
__device__ __forceinline__ uint2 gx16(int byteoff, int c) {
    return __ldg((const uint2*)((const char*)g_x16 + byteoff) + c);
}
__device__ __forceinline__ uint32_t gh216(int byteoff, int c) {
    return __ldg((const uint32_t*)((const char*)g_h216 + (byteoff >> 1)) + c);
}

// agg16[i] = half(di * (x16[i] + sum_j x16[src_j]))
__global__ void agg1_k(int n) {
    int w = (blockIdx.x * blockDim.x + threadIdx.x) >> 5;
    if (w >= n) return;
    int c = threadIdx.x & 31;
    float di = g_dinv[w];
    float4 sum = make_float4(0.f, 0.f, 0.f, 0.f);
    acc_x16(sum, __ldg((const uint2*)(g_x16 + (size_t)w * IND) + c));  // self
    int j = g_rowptr[w], end = g_rowptr[w + 1];
    for (; j + 7 < end; j += 8) {
        int s0 = __ldg(&g_csr_off[j]);
        int s1 = __ldg(&g_csr_off[j + 1]);
        int s2 = __ldg(&g_csr_off[j + 2]);
        int s3 = __ldg(&g_csr_off[j + 3]);
        int s4 = __ldg(&g_csr_off[j + 4]);
        int s5 = __ldg(&g_csr_off[j + 5]);
        int s6 = __ldg(&g_csr_off[j + 6]);
        int s7 = __ldg(&g_csr_off[j + 7]);
        uint2 p0 = gx16(s0, c);
        uint2 p1 = gx16(s1, c);
        uint2 p2 = gx16(s2, c);
        uint2 p3 = gx16(s3, c);
        uint2 p4 = gx16(s4, c);
        uint2 p5 = gx16(s5, c);
        uint2 p6 = gx16(s6, c);
        uint2 p7 = gx16(s7, c);
        acc_x16(sum, p0); acc_x16(sum, p1); acc_x16(sum, p2); acc_x16(sum, p3);
        acc_x16(sum, p4); acc_x16(sum, p5); acc_x16(sum, p6); acc_x16(sum, p7);
    }
    if (j + 3 < end) {
        int s0 = __ldg(&g_csr_off[j]);
        int s1 = __ldg(&g_csr_off[j + 1]);
        int s2 = __ldg(&g_csr_off[j + 2]);
        int s3 = __ldg(&g_csr_off[j + 3]);
        uint2 p0 = gx16(s0, c);
        uint2 p1 = gx16(s1, c);
        uint2 p2 = gx16(s2, c);
        uint2 p3 = gx16(s3, c);
        acc_x16(sum, p0); acc_x16(sum, p1); acc_x16(sum, p2); acc_x16(sum, p3);
        j += 4;
    }
    for (; j < end; j++) {
        int s = __ldg(&g_csr_off[j]);
        acc_x16(sum, gx16(s, c));
    }
    __half2 ha = __floats2half2_rn(sum.x * di, sum.y * di);
    __half2 hb = __floats2half2_rn(sum.z * di, sum.w * di);
    uint2 pk;
    pk.x = *(uint32_t*)&ha; pk.y = *(uint32_t*)&hb;
    *(uint2*)(g_agg16 + (size_t)w * IND + c * 4) = pk;
}

// out[i] = di * (h216[i] + sum_j h216[src_j]) + b2   (+ re-zero degc for next replay)
__global__ void agg2_k(const float* __restrict__ b2, float* __restrict__ out, int n) {
    int gi = blockIdx.x * blockDim.x + threadIdx.x;
    if (gi < n) g_degc[gi] = 0;        // restore invariant for next replay
    int w = gi >> 5;
    if (w >= n) return;
    int c = threadIdx.x & 31;
    float di = g_dinv[w];
    float2 bb = ((const float2*)b2)[c];
    float2 sum;
    {
        uint32_t p = __ldg((const uint32_t*)(g_h216 + (size_t)w * OUTD) + c);  // self
        sum = __half22float2(*(__half2*)&p);
    }
    int j = g_rowptr[w], end = g_rowptr[w + 1];
    for (; j + 7 < end; j += 8) {
        int s0 = __ldg(&g_csr_off[j]);
        int s1 = __ldg(&g_csr_off[j + 1]);
        int s2 = __ldg(&g_csr_off[j + 2]);
        int s3 = __ldg(&g_csr_off[j + 3]);
        int s4 = __ldg(&g_csr_off[j + 4]);
        int s5 = __ldg(&g_csr_off[j + 5]);
        int s6 = __ldg(&g_csr_off[j + 6]);
        int s7 = __ldg(&g_csr_off[j + 7]);
        uint32_t p0 = gh216(s0, c);
        uint32_t p1 = gh216(s1, c);
        uint32_t p2 = gh216(s2, c);
        uint32_t p3 = gh216(s3, c);
        uint32_t p4 = gh216(s4, c);
        uint32_t p5 = gh216(s5, c);
        uint32_t p6 = gh216(s6, c);
        uint32_t p7 = gh216(s7, c);
        float2 a0 = __half22float2(*(__half2*)&p0);
        float2 a1 = __half22float2(*(__half2*)&p1);
        float2 a2 = __half22float2(*(__half2*)&p2);
        float2 a3 = __half22float2(*(__half2*)&p3);
        float2 a4 = __half22float2(*(__half2*)&p4);
        float2 a5 = __half22float2(*(__half2*)&p5);
        float2 a6 = __half22float2(*(__half2*)&p6);
        float2 a7 = __half22float2(*(__half2*)&p7);
        sum.x += ((a0.x + a1.x) + (a2.x + a3.x)) + ((a4.x + a5.x) + (a6.x + a7.x));
        sum.y += ((a0.y + a1.y) + (a2.y + a3.y)) + ((a4.y + a5.y) + (a6.y + a7.y));
    }
    if (j + 3 < end) {
        int s0 = __ldg(&g_csr_off[j]);
        int s1 = __ldg(&g_csr_off[j + 1]);
        int s2 = __ldg(&g_csr_off[j + 2]);
        int s3 = __ldg(&g_csr_off[j + 3]);
        uint32_t p0 = gh216(s0, c);
        uint32_t p1 = gh216(s1, c);
        uint32_t p2 = gh216(s2, c);
        uint32_t p3 = gh216(s3, c);
        float2 a0 = __half22float2(*(__half2*)&p0);
        float2 a1 = __half22float2(*(__half2*)&p1);
        float2 a2 = __half22float2(*(__half2*)&p2);
        float2 a3 = __half22float2(*(__half2*)&p3);
        sum.x += (a0.x + a1.x) + (a2.x + a3.x);
        sum.y += (a0.y + a1.y) + (a2.y + a3.y);
        j += 4;
    }
    for (; j < end; j++) {
        int s = __ldg(&g_csr_off[j]);
        uint32_t p = gh216(s, c);
        float2 a = __half22float2(*(__half2*)&p);
        sum.x += a.x; sum.y += a.y;
    }
    float2 o;
    o.x = sum.x * di + bb.x;
    o.y = sum.y * di + bb.y;
    ((float2*)(out + (size_t)w * OUTD))[c] = o;
}

// ---------------- W prep (merged, single f16) ----------------
__global__ void wprep_k(const float* __restrict__ W1, const float* __restrict__ W2) {
    int i = blockIdx.x * blockDim.x + threadIdx.x;
    if (i < HID * IND) {
        int nn = i & 127, k = i >> 7;
        g_w1[nn * IND + k] = __float2half_rn(W1[k * HID + nn]);
    }
    int j = i - HID * IND;
    if (j >= 0 && j < OUTD * IND) {
        int nn = j & 63, k = j >> 6;
        g_w2[nn * IND + k] = __float2half_rn(W2[k * OUTD + nn]);
    }
}

// ---------------- fused HMMA GEMM1+GEMM2 (single-f16 W) ----------------
// Pass 1: h16 = relu(agg16 @ W1 + b1) -> written back into A smem (per-warp rows)
// Pass 2: h216 = half((h16 @ W2) * dinv) -> global
// smem = A(34816) + B1(34816) + B2(17408) = 87040 bytes -> 2 blocks/SM
#define LDA 136

__global__ __launch_bounds__(256) void gemmf_mma(const float* __restrict__ b1, int n) {
    extern __shared__ __half sm[];
    __half* Ah = sm;                     // 128*136 (A, then h16)
    __half* B1 = Ah + 128 * LDA;         // 128*136 ([n][k])
    __half* B2 = B1 + 128 * LDA;         // 64*136
    int tid = threadIdx.x, wid = tid >> 5, lane = tid & 31;
    int r0 = blockIdx.x * 128;

    for (int i = tid; i < 2048; i += 256) {
        int row = i >> 4, seg = i & 15;
        int gr = r0 + row;
        uint4 v = (gr < n) ? ((const uint4*)(g_agg16 + (size_t)gr * IND))[seg]
                           : make_uint4(0u, 0u, 0u, 0u);
        *(uint4*)(Ah + row * LDA + seg * 8) = v;
        *(uint4*)(B1 + row * LDA + seg * 8) = ((const uint4*)g_w1)[i];
    }
    for (int i = tid; i < 1024; i += 256) {
        int row = i >> 4, seg = i & 15;
        *(uint4*)(B2 + row * LDA + seg * 8) = ((const uint4*)g_w2)[i];
    }
    __syncthreads();

    uint32_t ah_b = smem_u32(Ah);
    uint32_t b1_b = smem_u32(B1);
    uint32_t b2_b = smem_u32(B2);
    int a_row = wid * 16 + (lane & 15);
    int a_co = (lane >> 4) * 8;
    uint32_t a_off = (uint32_t)(a_row * LDA + a_co) * 2;
    int b_row = (lane & 7) + ((lane >> 4) << 3);
    int b_co = ((lane >> 3) & 1) * 8;
    uint32_t b_off = (uint32_t)(b_row * LDA + b_co) * 2;

    int grp = lane >> 2, qid = lane & 3;
    int rowAl = wid * 16 + grp;
    int rowBl = rowAl + 8;

    // ---- pass 1: A @ W1 ----
    {
        float acc[16][4];
#pragma unroll
        for (int t = 0; t < 16; t++)
#pragma unroll
            for (int j = 0; j < 4; j++) acc[t][j] = 0.f;

#pragma unroll
        for (int ks = 0; ks < 8; ks++) {
            uint32_t ahr[4];
            ldm_x4(ahr, ah_b + a_off + ks * 32);
#pragma unroll
            for (int np = 0; np < 8; np++) {
                uint32_t bhr[4];
                ldm_x4(bhr, b1_b + b_off + (uint32_t)(np * 16 * LDA * 2) + ks * 32);
                mma16816(acc[2 * np], ahr, bhr);
                mma16816(acc[2 * np + 1], ahr, bhr + 2);
            }
        }
#pragma unroll
        for (int t = 0; t < 16; t++) {
            int col = t * 8 + qid * 2;
            float2 bb = *(const float2*)(b1 + col);
            *(__half2*)(Ah + rowAl * LDA + col) =
                __floats2half2_rn(fmaxf(acc[t][0] + bb.x, 0.f),
                                  fmaxf(acc[t][1] + bb.y, 0.f));
            *(__half2*)(Ah + rowBl * LDA + col) =
                __floats2half2_rn(fmaxf(acc[t][2] + bb.x, 0.f),
                                  fmaxf(acc[t][3] + bb.y, 0.f));
        }
    }
    __syncwarp();

    // ---- pass 2: h16 @ W2 ----
    {
        float acc[8][4];
#pragma unroll
        for (int t = 0; t < 8; t++)
#pragma unroll
            for (int j = 0; j < 4; j++) acc[t][j] = 0.f;

#pragma unroll
        for (int ks = 0; ks < 8; ks++) {
            uint32_t ahr[4];
            ldm_x4(ahr, ah_b + a_off + ks * 32);
#pragma unroll
            for (int np = 0; np < 4; np++) {
                uint32_t bhr[4];
                ldm_x4(bhr, b2_b + b_off + (uint32_t)(np * 16 * LDA * 2) + ks * 32);
                mma16816(acc[2 * np], ahr, bhr);
                mma16816(acc[2 * np + 1], ahr, bhr + 2);
            }
        }
        int rowA = r0 + rowAl;
        int rowB = r0 + rowBl;
        float dva = (rowA < n) ? g_dinv[rowA] : 0.f;
        float dvb = (rowB < n) ? g_dinv[rowB] : 0.f;
#pragma unroll
        for (int t = 0; t < 8; t++) {
            int col = t * 8 + qid * 2;
            if (rowA < n)
                *(__half2*)(g_h216 + (size_t)rowA * OUTD + col) =
                    __floats2half2_rn(acc[t][0] * dva, acc[t][1] * dva);
            if (rowB < n)
                *(__half2*)(g_h216 + (size_t)rowB * OUTD + col) =
                    __floats2half2_rn(acc[t][2] * dvb, acc[t][3] * dvb);
        }
    }
}

// ---------------- launch ----------------
extern "C" void kernel_launch(void* const* d_in, const int* in_sizes, int n_in,
                              void* d_out, int out_size) {
    const float* x  = (const float*)d_in[0];
    const int*   ei = (const int*)d_in[1];
    const float* W1 = (const float*)d_in[2];
    const float* b1 = (const float*)d_in[3];
    const float* W2 = (const float*)d_in[4];
    const float* b2 = (const float*)d_in[5];
    float* out      = (float*)d_out;

    int n = in_sizes[0] / IND;
    int E = in_sizes[1] / 2;
    const int* src = ei;
    const int* dst = ei + E;

    const int SMF = 2 * (128 * LDA * 2) + (64 * LDA * 2);  // 87040 -> 2 blocks/SM
    cudaFuncSetAttribute(gemmf_mma, cudaFuncAttributeMaxDynamicSharedMemorySize, SMF);

    const int TB = 256;
    int nb = (n + SCAN_B - 1) / SCAN_B;   // 98 <= 148: lookback co-residency holds
    int gblk = (n + 127) / 128;
    bool vec4 = (E % 4 == 0) && ((((uintptr_t)dst) & 15) == 0) && ((((uintptr_t)src) & 15) == 0);

    if (vec4) deg4_k<<<(E / 4 + TB - 1) / TB, TB>>>(dst, E / 4, E);
    else      deg_k<<<(E + TB - 1) / TB, TB>>>(dst, E);
    scanx_k<<<nb, SCAN_B>>>(x, n);
    if (vec4) scatter4_k<<<(E / 4 + TB - 1) / TB, TB>>>(src, dst, E / 4, E);
    else      scatter_k<<<(E + TB - 1) / TB, TB>>>(src, dst, E);

    int aggBlocks = (int)(((long long)n * 32 + TB - 1) / TB);
    agg1_k<<<aggBlocks, TB>>>(n);
    wprep_k<<<((HID + OUTD) * IND + TB - 1) / TB, TB>>>(W1, W2);
    gemmf_mma<<<gblk, TB, SMF>>>(b1, n);
    agg2_k<<<aggBlocks, TB>>>(b2, out, n);
}

// round 16
// speedup vs baseline: 1.2413x; 1.0048x over previous
#include <cuda_runtime.h>
#include <cuda_fp16.h>
#include <cstdint>

#define NMAX 100000
#define EMAX 2000000   // E + 3*NMAX padding headroom
#define IND 128
#define HID 128
#define OUTD 64
#define SCAN_B 1024
#define MAXBLK 128
#define WPREP_ELEMS ((HID + OUTD) * IND)   // 24576

// ---------------- scratch (static __device__, allocation-free) ----------------
__device__ int   g_degc[NMAX];
__device__ float g_dinv[NMAX];
__device__ int   g_rowptr[NMAX + 1];
__device__ int   g_pos[NMAX];
__device__ int   g_csr_off[EMAX];               // src byte-offset into g_x16 (src*256); rows padded to 4
__device__ unsigned long long g_scan_state[MAXBLK];
// Row NMAX of both tables is never written -> stays zero (padding target).
__device__ __half g_x16[(size_t)(NMAX + 1) * IND];
__device__ __half g_agg16[(size_t)NMAX * IND];
__device__ __half g_h216[(size_t)(NMAX + 1) * OUTD];
// W pre-transposed to [n][k], single f16 (rn-rounded)
__device__ __half g_w1[HID * IND];
__device__ __half g_w2[OUTD * IND];

__device__ __forceinline__ uint32_t smem_u32(const void* p) {
    uint32_t a;
    asm("{ .reg .u64 t; cvta.to.shared.u64 t, %1; cvt.u32.u64 %0, t; }" : "=r"(a) : "l"(p));
    return a;
}
__device__ __forceinline__ void ldm_x4(uint32_t* r, uint32_t addr) {
    asm volatile("ldmatrix.sync.aligned.m8n8.x4.shared.b16 {%0,%1,%2,%3}, [%4];"
                 : "=r"(r[0]), "=r"(r[1]), "=r"(r[2]), "=r"(r[3]) : "r"(addr));
}
__device__ __forceinline__ void mma16816(float* d, const uint32_t* a, const uint32_t* b) {
    asm volatile(
        "mma.sync.aligned.m16n8k16.row.col.f32.f16.f16.f32 "
        "{%0,%1,%2,%3}, {%4,%5,%6,%7}, {%8,%9}, {%0,%1,%2,%3};"
        : "+f"(d[0]), "+f"(d[1]), "+f"(d[2]), "+f"(d[3])
        : "r"(a[0]), "r"(a[1]), "r"(a[2]), "r"(a[3]), "r"(b[0]), "r"(b[1]));
}
__device__ __forceinline__ unsigned long long ldvol64(const unsigned long long* p) {
    unsigned long long v;
    asm volatile("ld.volatile.global.u64 %0, [%1];" : "=l"(v) : "l"(p));
    return v;
}
__device__ __forceinline__ void stvol64(unsigned long long* p, unsigned long long v) {
    asm volatile("st.volatile.global.u64 [%0], %1;" :: "l"(p), "l"(v));
}

// ---------------- CSR build ----------------
// NOTE: g_degc is zeroed by agg2_k at the end of each replay (and statically for call 1).
__global__ void deg4_k(const int* __restrict__ dst, int E4, int E) {
    int i = blockIdx.x * blockDim.x + threadIdx.x;
    if (i < MAXBLK) g_scan_state[i] = 0ULL;
    if (i < E4) {
        int4 d = ((const int4*)dst)[i];
        atomicAdd(&g_degc[d.x], 1);
        atomicAdd(&g_degc[d.y], 1);
        atomicAdd(&g_degc[d.z], 1);
        atomicAdd(&g_degc[d.w], 1);
    }
    if (i == 0)
        for (int k = E4 * 4; k < E; k++) atomicAdd(&g_degc[dst[k]], 1);
}
__global__ void deg_k(const int* __restrict__ dst, int E) {
    int i = blockIdx.x * blockDim.x + threadIdx.x;
    if (i < MAXBLK) g_scan_state[i] = 0ULL;
    if (i < E) atomicAdd(&g_degc[dst[i]], 1);
}

// Scan (decoupled lookback, PADDED degrees) + dinv + x16 conv + wprep (extra blocks).
// Scan blocks: [0, nb). Wprep blocks: [nb, nb + wb). Total grid <= 148 for co-residency.
__global__ __launch_bounds__(SCAN_B) void scanx_k(const float* __restrict__ x,
                                                  const float* __restrict__ W1,
                                                  const float* __restrict__ W2,
                                                  int n, int nb) {
    int b = blockIdx.x, t = threadIdx.x;

    if (b >= nb) {  // ---- wprep role (independent) ----
        int i = (b - nb) * SCAN_B + t;
        if (i < HID * IND) {
            int nn = i & 127, k = i >> 7;
            g_w1[nn * IND + k] = __float2half_rn(W1[k * HID + nn]);
        } else if (i < WPREP_ELEMS) {
            int j = i - HID * IND;
            int nn = j & 63, k = j >> 6;
            g_w2[nn * IND + k] = __float2half_rn(W2[k * OUTD + nn]);
        }
        return;
    }

    __shared__ int wsum[32];
    __shared__ int sprefix;
    int i = b * SCAN_B + t;
    int v = (i < n) ? g_degc[i] : 0;
    if (i < n) g_dinv[i] = rsqrtf((float)v + 1.0f);
    int pv = (v + 3) & ~3;                 // padded degree (multiple of 4)
    int lane = t & 31, w = t >> 5;
    int x_ = pv;
#pragma unroll
    for (int o = 1; o < 32; o <<= 1) {
        int y = __shfl_up_sync(0xffffffffu, x_, o);
        if (lane >= o) x_ += y;
    }
    if (lane == 31) wsum[w] = x_;
    __syncthreads();
    if (w == 0) {
        int s = wsum[lane];
#pragma unroll
        for (int o = 1; o < 32; o <<= 1) {
            int y = __shfl_up_sync(0xffffffffu, s, o);
            if (lane >= o) s += y;
        }
        wsum[lane] = s;
    }
    __syncthreads();
    int incl = x_ + (w > 0 ? wsum[w - 1] : 0);
    int total = wsum[31];

    if (w == 0) {
        if (lane == 0)
            stvol64(&g_scan_state[b],
                    ((unsigned long long)((b == 0) ? 2u : 1u) << 32) | (unsigned)total);
        __syncwarp();
        if (b > 0) {
            int P = 0;
            int i0 = b - 1;
            while (true) {
                int ii = i0 - lane;
                unsigned long long s = (ii >= 0) ? ldvol64(&g_scan_state[ii])
                                                 : (2ULL << 32);
                while (__any_sync(0xffffffffu, (s >> 32) == 0))
                    if ((s >> 32) == 0) s = ldvol64(&g_scan_state[ii]);
                int f = (int)(s >> 32);
                int val = (int)(unsigned)s;
                unsigned m = __ballot_sync(0xffffffffu, f == 2);
                int c;
                if (m) {
                    int L = __ffs(m) - 1;
                    c = (lane <= L) ? val : 0;
                } else c = val;
#pragma unroll
                for (int o = 16; o > 0; o >>= 1) c += __shfl_down_sync(0xffffffffu, c, o);
                c = __shfl_sync(0xffffffffu, c, 0);
                P += c;
                if (m) break;
                i0 -= 32;
            }
            if (lane == 0) {
                stvol64(&g_scan_state[b], (2ULL << 32) | (unsigned)(P + total));
                sprefix = P;
            }
        } else if (lane == 0) sprefix = 0;
    }
    __syncthreads();
    int excl = incl - pv + sprefix;        // FIX: subtract own padded degree, not warp prefix
    if (i < n) {
        g_rowptr[i] = excl;
        g_pos[i] = excl;
        // fill padding slots with the zero-row offset
        for (int k = excl + v; k < excl + pv; k++) g_csr_off[k] = NMAX << 8;
        if (i == n - 1) g_rowptr[n] = excl + pv;
    }
    // x16 conversion for this block's rows
    int base = b * SCAN_B;
    for (int idx = t; idx < SCAN_B * 16; idx += SCAN_B) {
        int row = base + (idx >> 4);
        if (row >= n) break;
        int seg = idx & 15;
        float dv = g_dinv[row];
        const float4* xp = (const float4*)(x + (size_t)row * IND + seg * 8);
        float4 a = xp[0], bb = xp[1];
        __half2 h0 = __floats2half2_rn(a.x * dv, a.y * dv);
        __half2 h1 = __floats2half2_rn(a.z * dv, a.w * dv);
        __half2 h2 = __floats2half2_rn(bb.x * dv, bb.y * dv);
        __half2 h3 = __floats2half2_rn(bb.z * dv, bb.w * dv);
        uint4 o;
        o.x = *(uint32_t*)&h0; o.y = *(uint32_t*)&h1;
        o.z = *(uint32_t*)&h2; o.w = *(uint32_t*)&h3;
        *(uint4*)(g_x16 + (size_t)row * IND + seg * 8) = o;
    }
}

// Scatter: store BYTE OFFSET into g_x16 (src * 256).
__global__ void scatter4_k(const int* __restrict__ src, const int* __restrict__ dst,
                           int E4, int E) {
    int i = blockIdx.x * blockDim.x + threadIdx.x;
    if (i < E4) {
        int4 s = ((const int4*)src)[i];
        int4 d = ((const int4*)dst)[i];
        g_csr_off[atomicAdd(&g_pos[d.x], 1)] = s.x << 8;
        g_csr_off[atomicAdd(&g_pos[d.y], 1)] = s.y << 8;
        g_csr_off[atomicAdd(&g_pos[d.z], 1)] = s.z << 8;
        g_csr_off[atomicAdd(&g_pos[d.w], 1)] = s.w << 8;
    }
    if (i == 0)
        for (int k = E4 * 4; k < E; k++)
            g_csr_off[atomicAdd(&g_pos[dst[k]], 1)] = src[k] << 8;
}
__global__ void scatter_k(const int* __restrict__ src, const int* __restrict__ dst, int E) {
    int e = blockIdx.x * blockDim.x + threadIdx.x;
    if (e < E) g_csr_off[atomicAdd(&g_pos[dst[e]], 1)] = src[e] << 8;
}

// ---------------- aggregation (CSR padded to 4, warp per dst, int4 offset loads) ----------------
__device__ __forceinline__ void acc_x16(float4& sum, uint2 p) {
    float2 a = __half22float2(*(__half2*)&p.x);
    float2 b = __half22float2(*(__half2*)&p.y);
    sum.x += a.x; sum.y += a.y; sum.z += b.x; sum.w += b.y;
}
__device__ __forceinline__ uint2 gx16(int byteoff, int c) {
    return __ldg((const uint2*)((const char*)g_x16 + byteoff) + c);
}
__device__ __forceinline__ uint32_t gh216(int byteoff, int c) {
    return __ldg((const uint32_t*)((const char*)g_h216 + (byteoff >> 1)) + c);
}

// agg16[i] = half(di * (x16[i] + sum_j x16[src_j]))
__global__ void agg1_k(int n) {
    int w = (blockIdx.x * blockDim.x + threadIdx.x) >> 5;
    if (w >= n) return;
    int c = threadIdx.x & 31;
    float di = g_dinv[w];
    float4 sum = make_float4(0.f, 0.f, 0.f, 0.f);
    acc_x16(sum, __ldg((const uint2*)(g_x16 + (size_t)w * IND) + c));  // self
    int j = g_rowptr[w], end = g_rowptr[w + 1];
    for (; j + 8 <= end; j += 8) {
        int4 o0 = *(const int4*)&g_csr_off[j];
        int4 o1 = *(const int4*)&g_csr_off[j + 4];
        uint2 p0 = gx16(o0.x, c);
        uint2 p1 = gx16(o0.y, c);
        uint2 p2 = gx16(o0.z, c);
        uint2 p3 = gx16(o0.w, c);
        uint2 p4 = gx16(o1.x, c);
        uint2 p5 = gx16(o1.y, c);
        uint2 p6 = gx16(o1.z, c);
        uint2 p7 = gx16(o1.w, c);
        acc_x16(sum, p0); acc_x16(sum, p1); acc_x16(sum, p2); acc_x16(sum, p3);
        acc_x16(sum, p4); acc_x16(sum, p5); acc_x16(sum, p6); acc_x16(sum, p7);
    }
    if (j < end) {  // exactly 4 remain (rows padded to multiple of 4)
        int4 o0 = *(const int4*)&g_csr_off[j];
        uint2 p0 = gx16(o0.x, c);
        uint2 p1 = gx16(o0.y, c);
        uint2 p2 = gx16(o0.z, c);
        uint2 p3 = gx16(o0.w, c);
        acc_x16(sum, p0); acc_x16(sum, p1); acc_x16(sum, p2); acc_x16(sum, p3);
    }
    __half2 ha = __floats2half2_rn(sum.x * di, sum.y * di);
    __half2 hb = __floats2half2_rn(sum.z * di, sum.w * di);
    uint2 pk;
    pk.x = *(uint32_t*)&ha; pk.y = *(uint32_t*)&hb;
    *(uint2*)(g_agg16 + (size_t)w * IND + c * 4) = pk;
}

// out[i] = di * (h216[i] + sum_j h216[src_j]) + b2   (+ re-zero degc for next replay)
__global__ void agg2_k(const float* __restrict__ b2, float* __restrict__ out, int n) {
    int gi = blockIdx.x * blockDim.x + threadIdx.x;
    if (gi < n) g_degc[gi] = 0;
    int w = gi >> 5;
    if (w >= n) return;
    int c = threadIdx.x & 31;
    float di = g_dinv[w];
    float2 bb = ((const float2*)b2)[c];
    float2 sum;
    {
        uint32_t p = __ldg((const uint32_t*)(g_h216 + (size_t)w * OUTD) + c);  // self
        sum = __half22float2(*(__half2*)&p);
    }
    int j = g_rowptr[w], end = g_rowptr[w + 1];
    for (; j + 8 <= end; j += 8) {
        int4 o0 = *(const int4*)&g_csr_off[j];
        int4 o1 = *(const int4*)&g_csr_off[j + 4];
        uint32_t p0 = gh216(o0.x, c);
        uint32_t p1 = gh216(o0.y, c);
        uint32_t p2 = gh216(o0.z, c);
        uint32_t p3 = gh216(o0.w, c);
        uint32_t p4 = gh216(o1.x, c);
        uint32_t p5 = gh216(o1.y, c);
        uint32_t p6 = gh216(o1.z, c);
        uint32_t p7 = gh216(o1.w, c);
        float2 a0 = __half22float2(*(__half2*)&p0);
        float2 a1 = __half22float2(*(__half2*)&p1);
        float2 a2 = __half22float2(*(__half2*)&p2);
        float2 a3 = __half22float2(*(__half2*)&p3);
        float2 a4 = __half22float2(*(__half2*)&p4);
        float2 a5 = __half22float2(*(__half2*)&p5);
        float2 a6 = __half22float2(*(__half2*)&p6);
        float2 a7 = __half22float2(*(__half2*)&p7);
        sum.x += ((a0.x + a1.x) + (a2.x + a3.x)) + ((a4.x + a5.x) + (a6.x + a7.x));
        sum.y += ((a0.y + a1.y) + (a2.y + a3.y)) + ((a4.y + a5.y) + (a6.y + a7.y));
    }
    if (j < end) {
        int4 o0 = *(const int4*)&g_csr_off[j];
        uint32_t p0 = gh216(o0.x, c);
        uint32_t p1 = gh216(o0.y, c);
        uint32_t p2 = gh216(o0.z, c);
        uint32_t p3 = gh216(o0.w, c);
        float2 a0 = __half22float2(*(__half2*)&p0);
        float2 a1 = __half22float2(*(__half2*)&p1);
        float2 a2 = __half22float2(*(__half2*)&p2);
        float2 a3 = __half22float2(*(__half2*)&p3);
        sum.x += (a0.x + a1.x) + (a2.x + a3.x);
        sum.y += (a0.y + a1.y) + (a2.y + a3.y);
    }
    float2 o;
    o.x = sum.x * di + bb.x;
    o.y = sum.y * di + bb.y;
    ((float2*)(out + (size_t)w * OUTD))[c] = o;
}

// ---------------- fused HMMA GEMM1+GEMM2 (single-f16 W) ----------------
#define LDA 136

__global__ __launch_bounds__(256) void gemmf_mma(const float* __restrict__ b1, int n) {
    extern __shared__ __half sm[];
    __half* Ah = sm;                     // 128*136 (A, then h16)
    __half* B1 = Ah + 128 * LDA;         // 128*136 ([n][k])
    __half* B2 = B1 + 128 * LDA;         // 64*136
    int tid = threadIdx.x, wid = tid >> 5, lane = tid & 31;
    int r0 = blockIdx.x * 128;

    for (int i = tid; i < 2048; i += 256) {
        int row = i >> 4, seg = i & 15;
        int gr = r0 + row;
        uint4 v = (gr < n) ? ((const uint4*)(g_agg16 + (size_t)gr * IND))[seg]
                           : make_uint4(0u, 0u, 0u, 0u);
        *(uint4*)(Ah + row * LDA + seg * 8) = v;
        *(uint4*)(B1 + row * LDA + seg * 8) = ((const uint4*)g_w1)[i];
    }
    for (int i = tid; i < 1024; i += 256) {
        int row = i >> 4, seg = i & 15;
        *(uint4*)(B2 + row * LDA + seg * 8) = ((const uint4*)g_w2)[i];
    }
    __syncthreads();

    uint32_t ah_b = smem_u32(Ah);
    uint32_t b1_b = smem_u32(B1);
    uint32_t b2_b = smem_u32(B2);
    int a_row = wid * 16 + (lane & 15);
    int a_co = (lane >> 4) * 8;
    uint32_t a_off = (uint32_t)(a_row * LDA + a_co) * 2;
    int b_row = (lane & 7) + ((lane >> 4) << 3);
    int b_co = ((lane >> 3) & 1) * 8;
    uint32_t b_off = (uint32_t)(b_row * LDA + b_co) * 2;

    int grp = lane >> 2, qid = lane & 3;
    int rowAl = wid * 16 + grp;
    int rowBl = rowAl + 8;

    // ---- pass 1: A @ W1 ----
    {
        float acc[16][4];
#pragma unroll
        for (int t = 0; t < 16; t++)
#pragma unroll
            for (int j = 0; j < 4; j++) acc[t][j] = 0.f;

#pragma unroll
        for (int ks = 0; ks < 8; ks++) {
            uint32_t ahr[4];
            ldm_x4(ahr, ah_b + a_off + ks * 32);
#pragma unroll
            for (int np = 0; np < 8; np++) {
                uint32_t bhr[4];
                ldm_x4(bhr, b1_b + b_off + (uint32_t)(np * 16 * LDA * 2) + ks * 32);
                mma16816(acc[2 * np], ahr, bhr);
                mma16816(acc[2 * np + 1], ahr, bhr + 2);
            }
        }
#pragma unroll
        for (int t = 0; t < 16; t++) {
            int col = t * 8 + qid * 2;
            float2 bb = *(const float2*)(b1 + col);
            *(__half2*)(Ah + rowAl * LDA + col) =
                __floats2half2_rn(fmaxf(acc[t][0] + bb.x, 0.f),
                                  fmaxf(acc[t][1] + bb.y, 0.f));
            *(__half2*)(Ah + rowBl * LDA + col) =
                __floats2half2_rn(fmaxf(acc[t][2] + bb.x, 0.f),
                                  fmaxf(acc[t][3] + bb.y, 0.f));
        }
    }
    __syncwarp();

    // ---- pass 2: h16 @ W2 ----
    {
        float acc[8][4];
#pragma unroll
        for (int t = 0; t < 8; t++)
#pragma unroll
            for (int j = 0; j < 4; j++) acc[t][j] = 0.f;

#pragma unroll
        for (int ks = 0; ks < 8; ks++) {
            uint32_t ahr[4];
            ldm_x4(ahr, ah_b + a_off + ks * 32);
#pragma unroll
            for (int np = 0; np < 4; np++) {
                uint32_t bhr[4];
                ldm_x4(bhr, b2_b + b_off + (uint32_t)(np * 16 * LDA * 2) + ks * 32);
                mma16816(acc[2 * np], ahr, bhr);
                mma16816(acc[2 * np + 1], ahr, bhr + 2);
            }
        }
        int rowA = r0 + rowAl;
        int rowB = r0 + rowBl;
        float dva = (rowA < n) ? g_dinv[rowA] : 0.f;
        float dvb = (rowB < n) ? g_dinv[rowB] : 0.f;
#pragma unroll
        for (int t = 0; t < 8; t++) {
            int col = t * 8 + qid * 2;
            if (rowA < n)
                *(__half2*)(g_h216 + (size_t)rowA * OUTD + col) =
                    __floats2half2_rn(acc[t][0] * dva, acc[t][1] * dva);
            if (rowB < n)
                *(__half2*)(g_h216 + (size_t)rowB * OUTD + col) =
                    __floats2half2_rn(acc[t][2] * dvb, acc[t][3] * dvb);
        }
    }
}

// ---------------- launch ----------------
extern "C" void kernel_launch(void* const* d_in, const int* in_sizes, int n_in,
                              void* d_out, int out_size) {
    const float* x  = (const float*)d_in[0];
    const int*   ei = (const int*)d_in[1];
    const float* W1 = (const float*)d_in[2];
    const float* b1 = (const float*)d_in[3];
    const float* W2 = (const float*)d_in[4];
    const float* b2 = (const float*)d_in[5];
    float* out      = (float*)d_out;

    int n = in_sizes[0] / IND;
    int E = in_sizes[1] / 2;
    const int* src = ei;
    const int* dst = ei + E;

    const int SMF = 2 * (128 * LDA * 2) + (64 * LDA * 2);  // 87040 -> 2 blocks/SM
    cudaFuncSetAttribute(gemmf_mma, cudaFuncAttributeMaxDynamicSharedMemorySize, SMF);

    const int TB = 256;
    int nb = (n + SCAN_B - 1) / SCAN_B;                    // 98
    int wb = (WPREP_ELEMS + SCAN_B - 1) / SCAN_B;          // 24
    int gblk = (n + 127) / 128;
    bool vec4 = (E % 4 == 0) && ((((uintptr_t)dst) & 15) == 0) && ((((uintptr_t)src) & 15) == 0);

    if (vec4) deg4_k<<<(E / 4 + TB - 1) / TB, TB>>>(dst, E / 4, E);
    else      deg_k<<<(E + TB - 1) / TB, TB>>>(dst, E);
    scanx_k<<<nb + wb, SCAN_B>>>(x, W1, W2, n, nb);        // 122 <= 148: co-resident
    if (vec4) scatter4_k<<<(E / 4 + TB - 1) / TB, TB>>>(src, dst, E / 4, E);
    else      scatter_k<<<(E + TB - 1) / TB, TB>>>(src, dst, E);

    int aggBlocks = (int)(((long long)n * 32 + TB - 1) / TB);
    agg1_k<<<aggBlocks, TB>>>(n);
    gemmf_mma<<<gblk, TB, SMF>>>(b1, n);
    agg2_k<<<aggBlocks, TB>>>(b2, out, n);
}